// round 3
// baseline (speedup 1.0000x reference)
#include <cuda_runtime.h>

// SSIM over (32,3,512,512) fp32 pairs, 7x7 box window, interior crop, scalar mean.
// Separable box filter. 2 columns per thread: horizontal 7-tap sums computed for
// col0, slid to col1 (S1 = S0 - tap0 + tap7). Rows staged in smem as float4
// (a0,b0,a1,b1) per column-pair -> 5 conflict-free LDS.128 taps per row/thread.
// Vertical 7-row sliding sums in register shift-rings. f32x2 packed math
// throughout, including the paired (A1,B1)/(A2,B2) SSIM epilogue.

#define W 512
#define H 512
#define NIMG 96           // 32 batch * 3 channels
#define NSTRIP 8
#define ROWS_OUT 64       // 8*64 = 512 >= 506 interior rows (tail masked)
#define NBLK (NIMG * NSTRIP)
#define NT 256            // threads per CTA; thread t owns cols 2t, 2t+1

typedef unsigned long long ull;

__device__ float g_part[NBLK];

__device__ __forceinline__ ull pk2(float lo, float hi) {
    ull r; asm("mov.b64 %0, {%1, %2};" : "=l"(r) : "f"(lo), "f"(hi)); return r;
}
__device__ __forceinline__ void upk2(ull v, float& lo, float& hi) {
    asm("mov.b64 {%0, %1}, %2;" : "=f"(lo), "=f"(hi) : "l"(v));
}
__device__ __forceinline__ ull add2(ull a, ull b) {
    ull r; asm("add.rn.f32x2 %0, %1, %2;" : "=l"(r) : "l"(a), "l"(b)); return r;
}
__device__ __forceinline__ ull mul2(ull a, ull b) {
    ull r; asm("mul.rn.f32x2 %0, %1, %2;" : "=l"(r) : "l"(a), "l"(b)); return r;
}
__device__ __forceinline__ ull fma2(ull a, ull b, ull c) {
    ull r; asm("fma.rn.f32x2 %0, %1, %2, %3;" : "=l"(r) : "l"(a), "l"(b), "l"(c)); return r;
}

__global__ void __launch_bounds__(NT) ssim_main(const float* __restrict__ A,
                                                const float* __restrict__ B) {
    // NP=49, CONV_NORM=49/48, C1=1e-4, C2=9e-4 (folded)
    const float C1 = 1e-4f;
    const float C2 = 9e-4f;

    const int t     = threadIdx.x;
    const int img   = blockIdx.x;
    const int strip = blockIdx.y;

    const size_t base = (size_t)img * (W * H);
    const float2* __restrict__ ap = (const float2*)(A + base) + t;  // + r*(W/2)
    const float2* __restrict__ bp = (const float2*)(B + base) + t;

    __shared__ ulonglong2 sbuf[2][NT];   // (a_even,b_even),(a_odd,b_odd) per pair

    // Loop-invariant tap pair-indices (clamped). Correct for all VALID output
    // columns: edge threads' clamped taps only feed masked columns.
    int p0 = min(max(t - 2, 0), NT - 1);
    int p1 = min(max(t - 1, 0), NT - 1);
    int p2 = t;
    int p3 = min(t + 1, NT - 1);
    int p4 = min(t + 2, NT - 1);

    const bool ok0 = (t >= 2) && (t <= 254);   // col 2t   in [3,508] (even: [4,508])
    const bool ok1 = (t >= 1) && (t <= 253);   // col 2t+1 in [3,508]

    const int rstart = strip * ROWS_OUT;

    const ull NEG1    = pk2(-1.0f, -1.0f);
    const ull K_INV49 = pk2(1.0f / 49.0f, 1.0f / 49.0f);
    const ull K21     = pk2(2.0f, 1.0f);
    const ull KC1     = pk2(C1, C1);
    const ull KC2     = pk2(C2, C2);
    const ull KP      = pk2(1.0f / 24.0f, 1.0f / 48.0f);    // (2CN/49, CN/49)
    const ull KM      = pk2(-49.0f / 24.0f, -49.0f / 48.0f);// (-2CN, -CN)

    // Vertical sliding state. vlinX=(Sa,Sb), vsqX=(Saa,Sbb) per column; v12
    // packed across columns: (Sab_c0, Sab_c1).
    ull vlin0 = 0, vlin1 = 0, vsq0 = 0, vsq1 = 0, v12 = 0;
    ull rl0[7] = {0,0,0,0,0,0,0}, rl1[7] = {0,0,0,0,0,0,0};
    ull rs0[7] = {0,0,0,0,0,0,0}, rs1[7] = {0,0,0,0,0,0,0};
    ull r12[7] = {0,0,0,0,0,0,0};
    float acc = 0.0f;

    float2 ra = __ldg(ap + rstart * (W / 2));
    float2 rb = __ldg(bp + rstart * (W / 2));
    int buf = 0;

    // 70 input rows = 10 groups of 7 (ring slot j == k%7 constant-folds)
    #pragma unroll 1
    for (int g = 0; g < 10; g++) {
        #pragma unroll
        for (int j = 0; j < 7; j++) {
            const int k = g * 7 + j;

            // Stage current row; prefetch next (row-clamped; fake rows only
            // reach masked outputs y>508).
            ulonglong2 st;
            st.x = pk2(ra.x, rb.x);
            st.y = pk2(ra.y, rb.y);
            sbuf[buf][t] = st;
            const int rn = min(rstart + k + 1, H - 1);
            ra = __ldg(ap + rn * (W / 2));
            rb = __ldg(bp + rn * (W / 2));
            __syncthreads();   // one barrier/row (double-buffered)

            // 8 taps (cols 2t-3 .. 2t+4) from 5 conflict-free LDS.128
            ulonglong2 s0 = sbuf[buf][p0];
            ulonglong2 s1 = sbuf[buf][p1];
            ulonglong2 s2 = sbuf[buf][p2];
            ulonglong2 s3 = sbuf[buf][p3];
            ulonglong2 s4 = sbuf[buf][p4];
            ull t0 = s0.y, t1 = s1.x, t2 = s1.y, t3 = s2.x;
            ull t4 = s2.y, t5 = s3.x, t6 = s3.y, t7 = s4.x;
            buf ^= 1;

            // Horizontal sums. col0 = taps 0..6; col1 = col0 - tap0 + tap7.
            ull L0 = add2(add2(add2(t0, t1), add2(t2, t3)),
                          add2(add2(t4, t5), t6));
            ull L1 = add2(fma2(t0, NEG1, L0), t7);

            ull q0 = mul2(t0, t0);
            ull Q0 = q0;
            Q0 = fma2(t1, t1, Q0); Q0 = fma2(t2, t2, Q0);
            Q0 = fma2(t3, t3, Q0); Q0 = fma2(t4, t4, Q0);
            Q0 = fma2(t5, t5, Q0); Q0 = fma2(t6, t6, Q0);
            ull Q1 = fma2(t7, t7, fma2(q0, NEG1, Q0));

            float a0, b0, a1, b1, a2, b2, a3, b3;
            float a4, b4, a5, b5, a6, b6, a7, b7;
            upk2(t0, a0, b0); upk2(t1, a1, b1); upk2(t2, a2, b2); upk2(t3, a3, b3);
            upk2(t4, a4, b4); upk2(t5, a5, b5); upk2(t6, a6, b6); upk2(t7, a7, b7);
            float pr0 = a0 * b0;
            float P0  = pr0;
            P0 = fmaf(a1, b1, P0); P0 = fmaf(a2, b2, P0); P0 = fmaf(a3, b3, P0);
            P0 = fmaf(a4, b4, P0); P0 = fmaf(a5, b5, P0); P0 = fmaf(a6, b6, P0);
            float P1 = fmaf(a7, b7, P0 - pr0);
            ull S12 = pk2(P0, P1);

            // Vertical sliding: v += new - ring[j]; ring[j] = new.
            vlin0 = fma2(rl0[j], NEG1, add2(vlin0, L0));  rl0[j] = L0;
            vlin1 = fma2(rl1[j], NEG1, add2(vlin1, L1));  rl1[j] = L1;
            vsq0  = fma2(rs0[j], NEG1, add2(vsq0,  Q0));  rs0[j] = Q0;
            vsq1  = fma2(rs1[j], NEG1, add2(vsq1,  Q1));  rs1[j] = Q1;
            v12   = fma2(r12[j], NEG1, add2(v12,  S12));  r12[j] = S12;

            if (k >= 6) {                      // full 7-row window -> emit
                const int y = rstart + k - 3;  // output row (center)
                const bool yok = (y <= H - 4);
                float s12c0, s12c1;
                upk2(v12, s12c0, s12c1);

                // ---- column 0 ----
                {
                    float ux, uy, v3, v4;
                    upk2(mul2(vlin0, K_INV49), ux, uy);
                    upk2(vsq0, v3, v4);
                    float tt = ux * uy;
                    float q2 = fmaf(uy, uy, ux * ux);
                    float sv = v3 + v4;
                    ull TQ  = pk2(tt, q2);
                    ull AB1 = fma2(TQ, K21, KC1);                      // (A1,B1)
                    ull AB2 = fma2(TQ, KM, fma2(pk2(s12c0, sv), KP, KC2)); // (A2,B2)
                    float N, D;
                    upk2(mul2(AB1, AB2), N, D);
                    float S = __fdividef(N, D);
                    acc += (ok0 && yok) ? S : 0.0f;
                }
                // ---- column 1 ----
                {
                    float ux, uy, v3, v4;
                    upk2(mul2(vlin1, K_INV49), ux, uy);
                    upk2(vsq1, v3, v4);
                    float tt = ux * uy;
                    float q2 = fmaf(uy, uy, ux * ux);
                    float sv = v3 + v4;
                    ull TQ  = pk2(tt, q2);
                    ull AB1 = fma2(TQ, K21, KC1);
                    ull AB2 = fma2(TQ, KM, fma2(pk2(s12c1, sv), KP, KC2));
                    float N, D;
                    upk2(mul2(AB1, AB2), N, D);
                    float S = __fdividef(N, D);
                    acc += (ok1 && yok) ? S : 0.0f;
                }
            }
        }
    }

    // Deterministic block reduction
    #pragma unroll
    for (int o = 16; o > 0; o >>= 1)
        acc += __shfl_xor_sync(0xFFFFFFFFu, acc, o);

    __shared__ float wsum[8];
    if ((t & 31) == 0) wsum[t >> 5] = acc;
    __syncthreads();
    if (t < 8) {
        float v = wsum[t];
        #pragma unroll
        for (int o = 4; o > 0; o >>= 1)
            v += __shfl_xor_sync(0xFFu, v, o);
        if (t == 0) g_part[blockIdx.y * NIMG + blockIdx.x] = v;
    }
}

__global__ void ssim_reduce(float* __restrict__ out) {
    const int t = threadIdx.x;
    double s = 0.0;
    for (int i = t; i < NBLK; i += 256) s += (double)g_part[i];
    __shared__ double sd[256];
    sd[t] = s;
    __syncthreads();
    for (int st = 128; st > 0; st >>= 1) {
        if (t < st) sd[t] += sd[t + st];
        __syncthreads();
    }
    if (t == 0)
        out[0] = (float)(sd[0] * (1.0 / ((double)NIMG * 506.0 * 506.0)));
}

extern "C" void kernel_launch(void* const* d_in, const int* in_sizes, int n_in,
                              void* d_out, int out_size) {
    const float* img1 = (const float*)d_in[0];
    const float* img2 = (const float*)d_in[1];
    float* out = (float*)d_out;
    (void)in_sizes; (void)n_in; (void)out_size;

    dim3 grid(NIMG, NSTRIP);
    ssim_main<<<grid, NT>>>(img1, img2);
    ssim_reduce<<<1, 256>>>(out);
}

// round 4
// speedup vs baseline: 2.0816x; 2.0816x over previous
#include <cuda_runtime.h>

// SSIM over (32,3,512,512) fp32 pairs, 7x7 box window, interior crop, scalar mean.
// Separable box filter, ALL-SCALAR fp32 (no f32x2 — sm_100a legalizes it badly).
// 2 columns/thread: horizontal 7-tap sums for col0, slid to col1 (S1=S0-t0+t7).
// Fields per column: La, Lb, Q(=Qa+Qb merged; epilogue only needs uxx+uyy), P(ab).
// Vertical 7-row sliding sums via register rings (56 floats). Rows staged in smem
// as float4 (a0,b0,a1,b1) -> 5 conflict-free LDS.128 taps per row/thread.
// Final reduction fused: last finished CTA sums partials in fixed order (double).

#define W 512
#define H 512
#define NIMG 96           // 32 batch * 3 channels
#define NSTRIP 8
#define ROWS_OUT 64
#define NBLK (NIMG * NSTRIP)
#define NT 256            // thread t owns cols 2t, 2t+1

__device__ float g_part[NBLK];
__device__ unsigned int g_count;   // zero-initialized; reset by last block each launch

__global__ void __launch_bounds__(NT, 2) ssim_main(const float* __restrict__ A,
                                                   const float* __restrict__ B,
                                                   float* __restrict__ out) {
    // NP=49, CONV_NORM=49/48, C1=1e-4, C2=9e-4 (folded)
    const float C1        = 1e-4f;
    const float C2        = 9e-4f;
    const float INV49     = 1.0f / 49.0f;
    const float CN        = 49.0f / 48.0f;
    const float TWO_CN    = 49.0f / 24.0f;
    const float CN_49     = 1.0f / 48.0f;    // CN/49
    const float TWO_CN_49 = 1.0f / 24.0f;    // 2*CN/49

    const int t    = threadIdx.x;
    const int blk  = blockIdx.x;
    const int img  = blk % NIMG;
    const int strip= blk / NIMG;

    const size_t base = (size_t)img * (W * H);
    const float2* __restrict__ ap = (const float2*)(A + base) + t;
    const float2* __restrict__ bp = (const float2*)(B + base) + t;

    __shared__ float4 sbuf[2][NT];   // (a_even, b_even, a_odd, b_odd)

    // Loop-invariant tap pair-indices (clamped; clamped taps only feed masked cols)
    const int p0 = max(t - 2, 0);
    const int p1 = max(t - 1, 0);
    const int p2 = t;
    const int p3 = min(t + 1, NT - 1);
    const int p4 = min(t + 2, NT - 1);

    const bool ok0 = (t >= 2) && (t <= 254);   // col 2t   valid (3..508)
    const bool ok1 = (t >= 1) && (t <= 253);   // col 2t+1 valid

    const int rstart = strip * ROWS_OUT;

    // Vertical sliding state (per column): La, Lb, Q, P
    float vA0 = 0.f, vB0 = 0.f, vQ0 = 0.f, vP0 = 0.f;
    float vA1 = 0.f, vB1 = 0.f, vQ1 = 0.f, vP1 = 0.f;
    float rA0[7] = {0,0,0,0,0,0,0}, rB0[7] = {0,0,0,0,0,0,0};
    float rQ0[7] = {0,0,0,0,0,0,0}, rP0[7] = {0,0,0,0,0,0,0};
    float rA1[7] = {0,0,0,0,0,0,0}, rB1[7] = {0,0,0,0,0,0,0};
    float rQ1[7] = {0,0,0,0,0,0,0}, rP1[7] = {0,0,0,0,0,0,0};
    float acc = 0.0f;

    float2 ra = __ldg(ap + rstart * (W / 2));
    float2 rb = __ldg(bp + rstart * (W / 2));
    int buf = 0;

    // 70 input rows = 10 groups of 7 (ring slot j == k%7 constant-folds)
    #pragma unroll 1
    for (int g = 0; g < 10; g++) {
        #pragma unroll
        for (int j = 0; j < 7; j++) {
            const int k = g * 7 + j;

            sbuf[buf][t] = make_float4(ra.x, rb.x, ra.y, rb.y);
            const int rn = min(rstart + k + 1, H - 1);
            ra = __ldg(ap + rn * (W / 2));
            rb = __ldg(bp + rn * (W / 2));
            __syncthreads();   // one barrier/row (double-buffered)

            // 8 taps (cols 2t-3 .. 2t+4) from 5 conflict-free LDS.128
            const float4 s0 = sbuf[buf][p0];
            const float4 s1 = sbuf[buf][p1];
            const float4 s2 = sbuf[buf][p2];
            const float4 s3 = sbuf[buf][p3];
            const float4 s4 = sbuf[buf][p4];
            const float a0 = s0.z, b0 = s0.w;
            const float a1 = s1.x, b1 = s1.y, a2 = s1.z, b2 = s1.w;
            const float a3 = s2.x, b3 = s2.y, a4 = s2.z, b4 = s2.w;
            const float a5 = s3.x, b5 = s3.y, a6 = s3.z, b6 = s3.w;
            const float a7 = s4.x, b7 = s4.y;
            buf ^= 1;

            // Horizontal 7-tap sums: col0 = taps 0..6; col1 = col0 - tap0 + tap7
            const float LA0 = ((a0 + a1) + (a2 + a3)) + ((a4 + a5) + a6);
            const float LB0 = ((b0 + b1) + (b2 + b3)) + ((b4 + b5) + b6);
            const float LA1 = (LA0 - a0) + a7;
            const float LB1 = (LB0 - b0) + b7;

            float Q0 = a0 * a0;
            Q0 = fmaf(b0, b0, Q0);
            Q0 = fmaf(a1, a1, Q0); Q0 = fmaf(b1, b1, Q0);
            Q0 = fmaf(a2, a2, Q0); Q0 = fmaf(b2, b2, Q0);
            Q0 = fmaf(a3, a3, Q0); Q0 = fmaf(b3, b3, Q0);
            Q0 = fmaf(a4, a4, Q0); Q0 = fmaf(b4, b4, Q0);
            Q0 = fmaf(a5, a5, Q0); Q0 = fmaf(b5, b5, Q0);
            Q0 = fmaf(a6, a6, Q0); Q0 = fmaf(b6, b6, Q0);
            float Q1 = fmaf(a7, a7, Q0);
            Q1 = fmaf(a0, -a0, Q1);
            Q1 = fmaf(b7, b7, Q1);
            Q1 = fmaf(b0, -b0, Q1);

            const float pr0 = a0 * b0;
            float P0 = pr0;
            P0 = fmaf(a1, b1, P0); P0 = fmaf(a2, b2, P0); P0 = fmaf(a3, b3, P0);
            P0 = fmaf(a4, b4, P0); P0 = fmaf(a5, b5, P0); P0 = fmaf(a6, b6, P0);
            const float P1 = fmaf(a7, b7, P0 - pr0);

            // Vertical sliding: v += new - ring[j]; ring[j] = new
            vA0 += LA0 - rA0[j];  rA0[j] = LA0;
            vB0 += LB0 - rB0[j];  rB0[j] = LB0;
            vQ0 += Q0  - rQ0[j];  rQ0[j] = Q0;
            vP0 += P0  - rP0[j];  rP0[j] = P0;
            vA1 += LA1 - rA1[j];  rA1[j] = LA1;
            vB1 += LB1 - rB1[j];  rB1[j] = LB1;
            vQ1 += Q1  - rQ1[j];  rQ1[j] = Q1;
            vP1 += P1  - rP1[j];  rP1[j] = P1;

            if (k >= 6) {                      // full 7x7 window -> emit
                const int  y   = rstart + k - 3;
                const bool yok = (y <= H - 4);
                // ---- column 0 ----
                {
                    const float ux = vA0 * INV49, uy = vB0 * INV49;
                    const float tt = ux * uy;
                    const float A1v = fmaf(tt, 2.0f, C1);
                    float A2v = fmaf(vP0, TWO_CN_49, C2);
                    A2v = fmaf(tt, -TWO_CN, A2v);
                    const float q2 = fmaf(uy, uy, ux * ux);
                    const float B1v = q2 + C1;
                    float B2v = fmaf(vQ0, CN_49, C2);
                    B2v = fmaf(q2, -CN, B2v);
                    const float S = __fdividef(A1v * A2v, B1v * B2v);
                    acc += (ok0 && yok) ? S : 0.0f;
                }
                // ---- column 1 ----
                {
                    const float ux = vA1 * INV49, uy = vB1 * INV49;
                    const float tt = ux * uy;
                    const float A1v = fmaf(tt, 2.0f, C1);
                    float A2v = fmaf(vP1, TWO_CN_49, C2);
                    A2v = fmaf(tt, -TWO_CN, A2v);
                    const float q2 = fmaf(uy, uy, ux * ux);
                    const float B1v = q2 + C1;
                    float B2v = fmaf(vQ1, CN_49, C2);
                    B2v = fmaf(q2, -CN, B2v);
                    const float S = __fdividef(A1v * A2v, B1v * B2v);
                    acc += (ok1 && yok) ? S : 0.0f;
                }
            }
        }
    }

    // Deterministic block reduction
    #pragma unroll
    for (int o = 16; o > 0; o >>= 1)
        acc += __shfl_xor_sync(0xFFFFFFFFu, acc, o);

    __shared__ float wsum[8];
    __shared__ bool  is_last;
    if ((t & 31) == 0) wsum[t >> 5] = acc;
    __syncthreads();
    if (t == 0) {
        float v = wsum[0] + wsum[1] + wsum[2] + wsum[3]
                + wsum[4] + wsum[5] + wsum[6] + wsum[7];
        g_part[blk] = v;
        __threadfence();
        unsigned int prev = atomicAdd(&g_count, 1u);
        is_last = (prev == NBLK - 1);
    }
    __syncthreads();

    // Last finished CTA: fixed-order double-precision final sum (deterministic)
    if (is_last) {
        double s = 0.0;
        for (int i = t; i < NBLK; i += NT) s += (double)__ldcg(&g_part[i]);
        __shared__ double sd[NT];
        sd[t] = s;
        __syncthreads();
        #pragma unroll
        for (int st = NT / 2; st > 0; st >>= 1) {
            if (t < st) sd[t] += sd[t + st];
            __syncthreads();
        }
        if (t == 0) {
            out[0] = (float)(sd[0] * (1.0 / ((double)NIMG * 506.0 * 506.0)));
            g_count = 0;   // reset for next graph replay
        }
    }
}

extern "C" void kernel_launch(void* const* d_in, const int* in_sizes, int n_in,
                              void* d_out, int out_size) {
    const float* img1 = (const float*)d_in[0];
    const float* img2 = (const float*)d_in[1];
    float* out = (float*)d_out;
    (void)in_sizes; (void)n_in; (void)out_size;

    ssim_main<<<NBLK, NT>>>(img1, img2, out);
}

// round 5
// speedup vs baseline: 2.4204x; 1.1628x over previous
#include <cuda_runtime.h>

// SSIM over (32,3,512,512) fp32 pairs, 7x7 box window, interior crop, scalar mean.
// Separable box filter, all-scalar fp32. 2 columns/thread; horizontal 7-tap sums
// for col0, slid to col1. Fields per column: La, Lb, Q(=Saa+Sbb), P(=Sab).
// Vertical 7-row sliding sums via register rings. Rows staged in smem as float4
// (a0,b0,a1,b1) -> 5 conflict-free LDS.128 taps/row/thread.
// NSTRIP=3 -> 288 CTAs = ONE full wave on 148 SMs x 2 CTAs (no wave tail).
// Final reduction fused via last-block-done (fixed-order double sum).

#define W 512
#define H 512
#define NIMG 96            // 32 batch * 3 channels
#define NSTRIP 3
#define ROWS_OUT 169       // 3*169 = 507 >= 506 interior rows (y>508 masked)
#define ROWS_IN  175       // ROWS_OUT + 6 = 25 groups of 7
#define NBLK (NIMG * NSTRIP)
#define NT 256             // thread t owns cols 2t, 2t+1

__device__ float g_part[NBLK];
__device__ unsigned int g_count;   // zero-init; reset by last block each launch

__device__ __forceinline__ float frcp(float x) {
    float r; asm("rcp.approx.f32 %0, %1;" : "=f"(r) : "f"(x)); return r;
}

__global__ void __launch_bounds__(NT, 2) ssim_main(const float* __restrict__ A,
                                                   const float* __restrict__ B,
                                                   float* __restrict__ out) {
    // NP=49, CONV_NORM=49/48, C1=1e-4, C2=9e-4 (folded)
    const float C1        = 1e-4f;
    const float C2        = 9e-4f;
    const float INV49     = 1.0f / 49.0f;
    const float CN        = 49.0f / 48.0f;
    const float TWO_CN    = 49.0f / 24.0f;
    const float CN_49     = 1.0f / 48.0f;    // CN/49
    const float TWO_CN_49 = 1.0f / 24.0f;    // 2*CN/49

    const int t     = threadIdx.x;
    const int blk   = blockIdx.x;
    const int img   = blk % NIMG;
    const int strip = blk / NIMG;

    const size_t base = (size_t)img * (W * H);
    const float2* __restrict__ ap = (const float2*)(A + base) + t;
    const float2* __restrict__ bp = (const float2*)(B + base) + t;

    __shared__ float4 sbuf[2][NT];   // (a_even, b_even, a_odd, b_odd)

    // Loop-invariant tap pair-indices (clamped taps feed only masked columns)
    const int p0 = max(t - 2, 0);
    const int p1 = max(t - 1, 0);
    const int p2 = t;
    const int p3 = min(t + 1, NT - 1);
    const int p4 = min(t + 2, NT - 1);

    const bool ok0 = (t >= 2) && (t <= 254);   // col 2t   in [3,508]
    const bool ok1 = (t >= 1) && (t <= 253);   // col 2t+1 in [3,508]

    const int rstart = strip * ROWS_OUT;       // 0 / 169 / 338

    // Vertical sliding state (per column): La, Lb, Q, P
    float vA0 = 0.f, vB0 = 0.f, vQ0 = 0.f, vP0 = 0.f;
    float vA1 = 0.f, vB1 = 0.f, vQ1 = 0.f, vP1 = 0.f;
    float rA0[7] = {0,0,0,0,0,0,0}, rB0[7] = {0,0,0,0,0,0,0};
    float rQ0[7] = {0,0,0,0,0,0,0}, rP0[7] = {0,0,0,0,0,0,0};
    float rA1[7] = {0,0,0,0,0,0,0}, rB1[7] = {0,0,0,0,0,0,0};
    float rQ1[7] = {0,0,0,0,0,0,0}, rP1[7] = {0,0,0,0,0,0,0};
    float acc = 0.0f;

    float2 ra = __ldg(ap + rstart * (W / 2));
    float2 rb = __ldg(bp + rstart * (W / 2));
    int buf = 0;

    // 175 input rows = 25 groups of 7 (ring slot j == k%7 constant-folds)
    #pragma unroll 1
    for (int g = 0; g < 25; g++) {
        #pragma unroll
        for (int j = 0; j < 7; j++) {
            const int k = g * 7 + j;

            sbuf[buf][t] = make_float4(ra.x, rb.x, ra.y, rb.y);
            // Row clamp only bites in strip 2 (rows >511 feed masked y>508 only)
            const int rn = min(rstart + k + 1, H - 1);
            ra = __ldg(ap + rn * (W / 2));
            rb = __ldg(bp + rn * (W / 2));
            __syncthreads();   // one barrier/row (double-buffered)

            // 8 taps (cols 2t-3 .. 2t+4) from 5 conflict-free LDS.128
            const float4 s0 = sbuf[buf][p0];
            const float4 s1 = sbuf[buf][p1];
            const float4 s2 = sbuf[buf][p2];
            const float4 s3 = sbuf[buf][p3];
            const float4 s4 = sbuf[buf][p4];
            const float a0 = s0.z, b0 = s0.w;
            const float a1 = s1.x, b1 = s1.y, a2 = s1.z, b2 = s1.w;
            const float a3 = s2.x, b3 = s2.y, a4 = s2.z, b4 = s2.w;
            const float a5 = s3.x, b5 = s3.y, a6 = s3.z, b6 = s3.w;
            const float a7 = s4.x, b7 = s4.y;
            buf ^= 1;

            // Horizontal 7-tap sums: col0 = taps 0..6; col1 = col0 - tap0 + tap7
            const float LA0 = ((a0 + a1) + (a2 + a3)) + ((a4 + a5) + a6);
            const float LB0 = ((b0 + b1) + (b2 + b3)) + ((b4 + b5) + b6);
            const float LA1 = (LA0 - a0) + a7;
            const float LB1 = (LB0 - b0) + b7;

            float Q0 = a0 * a0;
            Q0 = fmaf(b0, b0, Q0);
            Q0 = fmaf(a1, a1, Q0); Q0 = fmaf(b1, b1, Q0);
            Q0 = fmaf(a2, a2, Q0); Q0 = fmaf(b2, b2, Q0);
            Q0 = fmaf(a3, a3, Q0); Q0 = fmaf(b3, b3, Q0);
            Q0 = fmaf(a4, a4, Q0); Q0 = fmaf(b4, b4, Q0);
            Q0 = fmaf(a5, a5, Q0); Q0 = fmaf(b5, b5, Q0);
            Q0 = fmaf(a6, a6, Q0); Q0 = fmaf(b6, b6, Q0);
            float Q1 = fmaf(a7, a7, Q0);
            Q1 = fmaf(a0, -a0, Q1);
            Q1 = fmaf(b7, b7, Q1);
            Q1 = fmaf(b0, -b0, Q1);

            const float pr0 = a0 * b0;
            float P0 = pr0;
            P0 = fmaf(a1, b1, P0); P0 = fmaf(a2, b2, P0); P0 = fmaf(a3, b3, P0);
            P0 = fmaf(a4, b4, P0); P0 = fmaf(a5, b5, P0); P0 = fmaf(a6, b6, P0);
            const float P1 = fmaf(a7, b7, P0 - pr0);

            // Vertical sliding: v += new - ring[j]; ring[j] = new
            vA0 += LA0 - rA0[j];  rA0[j] = LA0;
            vB0 += LB0 - rB0[j];  rB0[j] = LB0;
            vQ0 += Q0  - rQ0[j];  rQ0[j] = Q0;
            vP0 += P0  - rP0[j];  rP0[j] = P0;
            vA1 += LA1 - rA1[j];  rA1[j] = LA1;
            vB1 += LB1 - rB1[j];  rB1[j] = LB1;
            vQ1 += Q1  - rQ1[j];  rQ1[j] = Q1;
            vP1 += P1  - rP1[j];  rP1[j] = P1;

            if (k >= 6) {                      // full 7x7 window -> emit
                const int  y   = rstart + k - 3;
                const bool yok = (y <= H - 4);

                // column 0 numerator/denominator
                const float ux0 = vA0 * INV49, uy0 = vB0 * INV49;
                const float tt0 = ux0 * uy0;
                const float A1v0 = fmaf(tt0, 2.0f, C1);
                float A2v0 = fmaf(vP0, TWO_CN_49, C2);
                A2v0 = fmaf(tt0, -TWO_CN, A2v0);
                const float q20 = fmaf(uy0, uy0, ux0 * ux0);
                const float B1v0 = q20 + C1;
                float B2v0 = fmaf(vQ0, CN_49, C2);
                B2v0 = fmaf(q20, -CN, B2v0);
                const float N0 = A1v0 * A2v0;
                const float D0 = B1v0 * B2v0;

                // column 1
                const float ux1 = vA1 * INV49, uy1 = vB1 * INV49;
                const float tt1 = ux1 * uy1;
                const float A1v1 = fmaf(tt1, 2.0f, C1);
                float A2v1 = fmaf(vP1, TWO_CN_49, C2);
                A2v1 = fmaf(tt1, -TWO_CN, A2v1);
                const float q21 = fmaf(uy1, uy1, ux1 * ux1);
                const float B1v1 = q21 + C1;
                float B2v1 = fmaf(vQ1, CN_49, C2);
                B2v1 = fmaf(q21, -CN, B2v1);
                const float N1 = A1v1 * A2v1;
                const float D1 = B1v1 * B2v1;

                // one reciprocal for both columns
                const float R = frcp(D0 * D1);
                const float S0 = N0 * D1 * R;
                const float S1 = N1 * D0 * R;
                acc += (ok0 && yok) ? S0 : 0.0f;
                acc += (ok1 && yok) ? S1 : 0.0f;
            }
        }
    }

    // Deterministic block reduction
    #pragma unroll
    for (int o = 16; o > 0; o >>= 1)
        acc += __shfl_xor_sync(0xFFFFFFFFu, acc, o);

    __shared__ float wsum[8];
    __shared__ bool  is_last;
    if ((t & 31) == 0) wsum[t >> 5] = acc;
    __syncthreads();
    if (t == 0) {
        float v = wsum[0] + wsum[1] + wsum[2] + wsum[3]
                + wsum[4] + wsum[5] + wsum[6] + wsum[7];
        g_part[blk] = v;
        __threadfence();
        unsigned int prev = atomicAdd(&g_count, 1u);
        is_last = (prev == NBLK - 1);
    }
    __syncthreads();

    // Last finished CTA: fixed-order double-precision final sum (deterministic)
    if (is_last) {
        double s = 0.0;
        for (int i = t; i < NBLK; i += NT) s += (double)__ldcg(&g_part[i]);
        __shared__ double sd[NT];
        sd[t] = s;
        __syncthreads();
        #pragma unroll
        for (int st = NT / 2; st > 0; st >>= 1) {
            if (t < st) sd[t] += sd[t + st];
            __syncthreads();
        }
        if (t == 0) {
            out[0] = (float)(sd[0] * (1.0 / ((double)NIMG * 506.0 * 506.0)));
            g_count = 0;   // reset for next graph replay
        }
    }
}

extern "C" void kernel_launch(void* const* d_in, const int* in_sizes, int n_in,
                              void* d_out, int out_size) {
    const float* img1 = (const float*)d_in[0];
    const float* img2 = (const float*)d_in[1];
    float* out = (float*)d_out;
    (void)in_sizes; (void)n_in; (void)out_size;

    ssim_main<<<NBLK, NT>>>(img1, img2, out);
}

// round 6
// speedup vs baseline: 2.6859x; 1.1097x over previous
#include <cuda_runtime.h>

// SSIM over (32,3,512,512) fp32 pairs, 7x7 box window, interior crop, scalar mean.
// Separable box filter, all-scalar fp32. 2 columns/thread; horizontal 7-tap sums
// for col0, slid to col1. Fields per column: La, Lb, Q(=Saa+Sbb), P(=Sab).
// Vertical 7-row sliding sums via register rings (slots compile-time, period 7).
// TWO ROWS PER BARRIER: rows k,k+1 staged into a 4-row smem ring, one
// __syncthreads per pair -> half the barriers, double the independent work per
// barrier interval (latency hiding). 182-row padded loop (13 x 14); padded rows
// are clamped reads with emits masked. NSTRIP=3 -> 288 CTAs = one full wave.
// Final reduction fused via last-block-done (fixed-order double sum).

#define W 512
#define H 512
#define NIMG 96            // 32 batch * 3 channels
#define NSTRIP 3
#define ROWS_OUT 169       // 3*169 = 507 >= 506 interior rows
#define NBLK (NIMG * NSTRIP)
#define NT 256             // thread t owns cols 2t, 2t+1

__device__ float g_part[NBLK];
__device__ unsigned int g_count;   // zero-init; reset by last block each launch

__device__ __forceinline__ float frcp(float x) {
    float r; asm("rcp.approx.f32 %0, %1;" : "=f"(r) : "f"(x)); return r;
}

// Process one staged row: taps from sbuf[BUFI], ring slot J (compile-time),
// global row-in-strip index KK (emit masked by [6, klim]).
#define PROC_ROW(BUFI, J, KK)                                                 \
do {                                                                          \
    const float4 s0 = sbuf[BUFI][p0];                                         \
    const float4 s1 = sbuf[BUFI][p1];                                         \
    const float4 s2 = sbuf[BUFI][p2];                                         \
    const float4 s3 = sbuf[BUFI][p3];                                         \
    const float4 s4 = sbuf[BUFI][p4];                                         \
    const float a0 = s0.z, b0 = s0.w;                                         \
    const float a1 = s1.x, b1 = s1.y, a2 = s1.z, b2 = s1.w;                   \
    const float a3 = s2.x, b3 = s2.y, a4 = s2.z, b4 = s2.w;                   \
    const float a5 = s3.x, b5 = s3.y, a6 = s3.z, b6 = s3.w;                   \
    const float a7 = s4.x, b7 = s4.y;                                         \
    const float LA0 = ((a0 + a1) + (a2 + a3)) + ((a4 + a5) + a6);             \
    const float LB0 = ((b0 + b1) + (b2 + b3)) + ((b4 + b5) + b6);             \
    const float LA1 = (LA0 - a0) + a7;                                        \
    const float LB1 = (LB0 - b0) + b7;                                        \
    float Q0 = a0 * a0;                                                       \
    Q0 = fmaf(b0, b0, Q0);                                                    \
    Q0 = fmaf(a1, a1, Q0); Q0 = fmaf(b1, b1, Q0);                             \
    Q0 = fmaf(a2, a2, Q0); Q0 = fmaf(b2, b2, Q0);                             \
    Q0 = fmaf(a3, a3, Q0); Q0 = fmaf(b3, b3, Q0);                             \
    Q0 = fmaf(a4, a4, Q0); Q0 = fmaf(b4, b4, Q0);                             \
    Q0 = fmaf(a5, a5, Q0); Q0 = fmaf(b5, b5, Q0);                             \
    Q0 = fmaf(a6, a6, Q0); Q0 = fmaf(b6, b6, Q0);                             \
    float Q1 = fmaf(a7, a7, Q0);                                              \
    Q1 = fmaf(a0, -a0, Q1);                                                   \
    Q1 = fmaf(b7, b7, Q1);                                                    \
    Q1 = fmaf(b0, -b0, Q1);                                                   \
    const float pr0 = a0 * b0;                                                \
    float P0 = pr0;                                                           \
    P0 = fmaf(a1, b1, P0); P0 = fmaf(a2, b2, P0); P0 = fmaf(a3, b3, P0);      \
    P0 = fmaf(a4, b4, P0); P0 = fmaf(a5, b5, P0); P0 = fmaf(a6, b6, P0);      \
    const float P1 = fmaf(a7, b7, P0 - pr0);                                  \
    vA0 += LA0 - rA0[J];  rA0[J] = LA0;                                       \
    vB0 += LB0 - rB0[J];  rB0[J] = LB0;                                       \
    vQ0 += Q0  - rQ0[J];  rQ0[J] = Q0;                                        \
    vP0 += P0  - rP0[J];  rP0[J] = P0;                                        \
    vA1 += LA1 - rA1[J];  rA1[J] = LA1;                                       \
    vB1 += LB1 - rB1[J];  rB1[J] = LB1;                                       \
    vQ1 += Q1  - rQ1[J];  rQ1[J] = Q1;                                        \
    vP1 += P1  - rP1[J];  rP1[J] = P1;                                        \
    {                                                                         \
        const bool yok = ((KK) >= 6) && ((KK) <= klim);                       \
        const float ux0 = vA0 * INV49, uy0 = vB0 * INV49;                     \
        const float tt0 = ux0 * uy0;                                          \
        const float A1v0 = fmaf(tt0, 2.0f, C1);                               \
        float A2v0 = fmaf(vP0, TWO_CN_49, C2);                                \
        A2v0 = fmaf(tt0, -TWO_CN, A2v0);                                      \
        const float q20 = fmaf(uy0, uy0, ux0 * ux0);                          \
        const float B1v0 = q20 + C1;                                          \
        float B2v0 = fmaf(vQ0, CN_49, C2);                                    \
        B2v0 = fmaf(q20, -CN, B2v0);                                          \
        const float N0 = A1v0 * A2v0;                                         \
        const float D0 = B1v0 * B2v0;                                         \
        const float ux1 = vA1 * INV49, uy1 = vB1 * INV49;                     \
        const float tt1 = ux1 * uy1;                                          \
        const float A1v1 = fmaf(tt1, 2.0f, C1);                               \
        float A2v1 = fmaf(vP1, TWO_CN_49, C2);                                \
        A2v1 = fmaf(tt1, -TWO_CN, A2v1);                                      \
        const float q21 = fmaf(uy1, uy1, ux1 * ux1);                          \
        const float B1v1 = q21 + C1;                                          \
        float B2v1 = fmaf(vQ1, CN_49, C2);                                    \
        B2v1 = fmaf(q21, -CN, B2v1);                                          \
        const float N1 = A1v1 * A2v1;                                         \
        const float D1 = B1v1 * B2v1;                                         \
        const float R = frcp(D0 * D1);                                        \
        const float S0 = N0 * D1 * R;                                         \
        const float S1 = N1 * D0 * R;                                         \
        acc += (ok0 && yok) ? S0 : 0.0f;                                      \
        acc += (ok1 && yok) ? S1 : 0.0f;                                      \
    }                                                                         \
} while (0)

__global__ void __launch_bounds__(NT, 2) ssim_main(const float* __restrict__ A,
                                                   const float* __restrict__ B,
                                                   float* __restrict__ out) {
    // NP=49, CONV_NORM=49/48, C1=1e-4, C2=9e-4 (folded)
    const float C1        = 1e-4f;
    const float C2        = 9e-4f;
    const float INV49     = 1.0f / 49.0f;
    const float CN        = 49.0f / 48.0f;
    const float TWO_CN    = 49.0f / 24.0f;
    const float CN_49     = 1.0f / 48.0f;    // CN/49
    const float TWO_CN_49 = 1.0f / 24.0f;    // 2*CN/49

    const int t     = threadIdx.x;
    const int blk   = blockIdx.x;
    const int img   = blk % NIMG;
    const int strip = blk / NIMG;

    const size_t base = (size_t)img * (W * H);
    const float2* __restrict__ ap = (const float2*)(A + base) + t;
    const float2* __restrict__ bp = (const float2*)(B + base) + t;

    __shared__ float4 sbuf[4][NT];   // 4-row ring of (a_even,b_even,a_odd,b_odd)

    // Loop-invariant tap pair-indices (clamped taps feed only masked columns)
    const int p0 = max(t - 2, 0);
    const int p1 = max(t - 1, 0);
    const int p2 = t;
    const int p3 = min(t + 1, NT - 1);
    const int p4 = min(t + 2, NT - 1);

    const bool ok0 = (t >= 2) && (t <= 254);   // col 2t   in [3,508]
    const bool ok1 = (t >= 1) && (t <= 253);   // col 2t+1 in [3,508]

    const int rstart = strip * ROWS_OUT;       // 0 / 169 / 338
    // Last emitting row index: strips 0,1 -> k=174 (169 outputs each);
    // strip 2 -> k=173 (y<=508, 168 outputs). Total 506.
    const int klim = (strip == 2) ? 173 : 174;

    // Vertical sliding state (per column): La, Lb, Q, P
    float vA0 = 0.f, vB0 = 0.f, vQ0 = 0.f, vP0 = 0.f;
    float vA1 = 0.f, vB1 = 0.f, vQ1 = 0.f, vP1 = 0.f;
    float rA0[7] = {0,0,0,0,0,0,0}, rB0[7] = {0,0,0,0,0,0,0};
    float rQ0[7] = {0,0,0,0,0,0,0}, rP0[7] = {0,0,0,0,0,0,0};
    float rA1[7] = {0,0,0,0,0,0,0}, rB1[7] = {0,0,0,0,0,0,0};
    float rQ1[7] = {0,0,0,0,0,0,0}, rP1[7] = {0,0,0,0,0,0,0};
    float acc = 0.0f;

    // Prefetch rows 0,1 of the strip
    float2 ra0 = __ldg(ap + (rstart + 0) * (W / 2));
    float2 rb0 = __ldg(bp + (rstart + 0) * (W / 2));
    float2 ra1 = __ldg(ap + (rstart + 1) * (W / 2));
    float2 rb1 = __ldg(bp + (rstart + 1) * (W / 2));

    int bufp = 0;   // buffer pair base: 0 or 2 (toggled per row-pair)

    // 182 rows = 13 x (7 pairs). Ring slot = row%7 is compile-time (14%7==0).
    // Rows 175..181 are clamped re-reads; their emits exceed klim (masked).
    #pragma unroll 1
    for (int it = 0; it < 13; it++) {
        const int kb = it * 14;
        #pragma unroll
        for (int m = 0; m < 7; m++) {
            const int k0 = kb + 2 * m;       // kb runtime, offset compile-time

            sbuf[bufp    ][t] = make_float4(ra0.x, rb0.x, ra0.y, rb0.y);
            sbuf[bufp + 1][t] = make_float4(ra1.x, rb1.x, ra1.y, rb1.y);

            const int rn0 = min(rstart + k0 + 2, H - 1);
            const int rn1 = min(rstart + k0 + 3, H - 1);
            ra0 = __ldg(ap + rn0 * (W / 2));
            rb0 = __ldg(bp + rn0 * (W / 2));
            ra1 = __ldg(ap + rn1 * (W / 2));
            rb1 = __ldg(bp + rn1 * (W / 2));

            __syncthreads();                 // one barrier per TWO rows

            PROC_ROW(bufp,     (2 * m) % 7,     k0);
            PROC_ROW(bufp + 1, (2 * m + 1) % 7, k0 + 1);

            bufp ^= 2;
        }
    }

    // Deterministic block reduction
    #pragma unroll
    for (int o = 16; o > 0; o >>= 1)
        acc += __shfl_xor_sync(0xFFFFFFFFu, acc, o);

    __shared__ float wsum[8];
    __shared__ bool  is_last;
    if ((t & 31) == 0) wsum[t >> 5] = acc;
    __syncthreads();
    if (t == 0) {
        float v = wsum[0] + wsum[1] + wsum[2] + wsum[3]
                + wsum[4] + wsum[5] + wsum[6] + wsum[7];
        g_part[blk] = v;
        __threadfence();
        unsigned int prev = atomicAdd(&g_count, 1u);
        is_last = (prev == NBLK - 1);
    }
    __syncthreads();

    // Last finished CTA: fixed-order double-precision final sum (deterministic)
    if (is_last) {
        double s = 0.0;
        for (int i = t; i < NBLK; i += NT) s += (double)__ldcg(&g_part[i]);
        __shared__ double sd[NT];
        sd[t] = s;
        __syncthreads();
        #pragma unroll
        for (int st = NT / 2; st > 0; st >>= 1) {
            if (t < st) sd[t] += sd[t + st];
            __syncthreads();
        }
        if (t == 0) {
            out[0] = (float)(sd[0] * (1.0 / ((double)NIMG * 506.0 * 506.0)));
            g_count = 0;   // reset for next graph replay
        }
    }
}

extern "C" void kernel_launch(void* const* d_in, const int* in_sizes, int n_in,
                              void* d_out, int out_size) {
    const float* img1 = (const float*)d_in[0];
    const float* img2 = (const float*)d_in[1];
    float* out = (float*)d_out;
    (void)in_sizes; (void)n_in; (void)out_size;

    ssim_main<<<NBLK, NT>>>(img1, img2, out);
}